// round 15
// baseline (speedup 1.0000x reference)
#include <cuda_runtime.h>
#include <math.h>
#include <stdint.h>

#define BB   2
#define TT   2048
#define DD   1024
#define NH   16
#define NKV  4
#define HD   64
#define KD   256
#define RANK 8
#define NTOK (BB*TT)
#define GQ   (NH/NKV)
#define KVW  512                 // combined k|v row width

// scratch (static device allocations — allowed)
__device__ float g_Wq_hi[DD*DD],  g_Wq_lo[DD*DD];
__device__ float g_Wkv_hi[KVW*DD], g_Wkv_lo[KVW*DD];
__device__ float g_Wp_hi[DD*DD],  g_Wp_lo[DD*DD];
__device__ float g_x_hi[NTOK*DD], g_x_lo[NTOK*DD];
__device__ float g_q[NTOK*DD];
__device__ float g_kv[NTOK*KVW];            // cols 0..255 = k, 256..511 = v
__device__ float g_y_hi[NTOK*DD], g_y_lo[NTOK*DD];

// ---------------- helpers ---------------------------------------------------
__device__ __forceinline__ float to_tf32(float x) {
    uint32_t u; asm("cvt.rna.tf32.f32 %0, %1;" : "=r"(u) : "f"(x));
    return __uint_as_float(u);
}
__device__ __forceinline__ uint32_t f2u(float x) { return __float_as_uint(x); }

__device__ __forceinline__ void mma_tf32(float& c0, float& c1, float& c2, float& c3,
                                         uint32_t a0, uint32_t a1, uint32_t a2, uint32_t a3,
                                         uint32_t b0, uint32_t b1) {
    asm volatile(
        "mma.sync.aligned.m16n8k8.row.col.f32.tf32.tf32.f32 "
        "{%0,%1,%2,%3}, {%4,%5,%6,%7}, {%8,%9}, {%0,%1,%2,%3};"
        : "+f"(c0), "+f"(c1), "+f"(c2), "+f"(c3)
        : "r"(a0), "r"(a1), "r"(a2), "r"(a3), "r"(b0), "r"(b1));
}

// ---------------------------------------------------------------------------
// prep kernels: split inputs/weights into tf32 hi/lo once.
// ---------------------------------------------------------------------------
__global__ void split_hl(const float* __restrict__ in, float* __restrict__ hi,
                         float* __restrict__ lo, int n) {
    int i = blockIdx.x * blockDim.x + threadIdx.x;
    if (i >= n) return;
    float v = in[i];
    float h = to_tf32(v);
    hi[i] = h; lo[i] = to_tf32(v - h);
}

__global__ void merge_wq_split(const float* __restrict__ W, const float* __restrict__ Am,
                               const float* __restrict__ Bm,
                               float* __restrict__ hi, float* __restrict__ lo) {
    int idx = blockIdx.x * blockDim.x + threadIdx.x;
    if (idx >= DD * DD) return;
    int o = idx >> 10, d = idx & 1023;
    float acc = W[idx];
#pragma unroll
    for (int r = 0; r < RANK; r++) acc += Bm[o*RANK + r] * Am[r*DD + d];
    float h = to_tf32(acc);
    hi[idx] = h; lo[idx] = to_tf32(acc - h);
}

// rows 0..255 = Wk (no LoRA), rows 256..511 = Wv + Bv@Av
__global__ void merge_wkv_split(const float* __restrict__ Wk, const float* __restrict__ Wv,
                                const float* __restrict__ Av, const float* __restrict__ Bv,
                                float* __restrict__ hi, float* __restrict__ lo) {
    int idx = blockIdx.x * blockDim.x + threadIdx.x;
    if (idx >= KVW * DD) return;
    int o = idx >> 10, d = idx & 1023;
    float acc;
    if (o < KD) {
        acc = Wk[o*DD + d];
    } else {
        int ov = o - KD;
        acc = Wv[ov*DD + d];
#pragma unroll
        for (int r = 0; r < RANK; r++) acc += Bv[ov*RANK + r] * Av[r*DD + d];
    }
    float h = to_tf32(acc);
    hi[idx] = h; lo[idx] = to_tf32(acc - h);
}

// ---------------------------------------------------------------------------
// gemm_mma4: tf32x3 GEMM on pre-split inputs.  C = A @ W^T.
// 128x128 CTA tile, BK=32, 2-stage double buffer (ONE sync per chunk),
// interleaved (hi,lo) smem rows -> LDS.64 fragment loads, STS.128 stores.
// 8 warps x (64x32) m16n8k8; fragment mapping identical to gemm_mma3.
// ---------------------------------------------------------------------------
#define GROW 68                       // floats per smem row (32 k * 2 + pad 4)
#define GSTG (256 * GROW)             // floats per stage (A 128 rows + B 128 rows)

__global__ __launch_bounds__(256, 1)
void gemm_mma4(const float* __restrict__ Ahi, const float* __restrict__ Alo,
               const float* __restrict__ Bhi, const float* __restrict__ Blo,
               float* __restrict__ C, int M, int N, int K) {
    extern __shared__ __align__(16) float sgm[];
    int tid = threadIdx.x;
    int wid = tid >> 5, lane = tid & 31;
    int g = lane >> 2, tg = lane & 3;
    int wm = wid >> 2, wn = wid & 3;
    int m0 = blockIdx.y << 7, n0 = blockIdx.x << 7;

    const float* ahp = Ahi + (size_t)m0 * K;
    const float* alp = Alo + (size_t)m0 * K;
    const float* bhp = Bhi + (size_t)n0 * K;
    const float* blp = Blo + (size_t)n0 * K;

    float acc[4][4][4];
#pragma unroll
    for (int mt = 0; mt < 4; mt++)
#pragma unroll
        for (int nt = 0; nt < 4; nt++)
#pragma unroll
            for (int r = 0; r < 4; r++) acc[mt][nt][r] = 0.f;

    int nk = K >> 5;
    // per-thread staging: c = it*256+tid -> row r=c>>3 (0..127), k-offset c4=(c&7)*4
    float4 ha[4], la[4], hb[4], lb[4];

    auto loadregs = [&](int k0) {
        int koff = k0 * 32;
#pragma unroll
        for (int it = 0; it < 4; it++) {
            int c = it * 256 + tid, r = c >> 3, c4 = (c & 7) << 2;
            size_t off = (size_t)r * K + koff + c4;
            ha[it] = *(const float4*)(ahp + off);
            la[it] = *(const float4*)(alp + off);
            hb[it] = *(const float4*)(bhp + off);
            lb[it] = *(const float4*)(blp + off);
        }
    };
    auto storestage = [&](int s) {
        float* sa = sgm + s * GSTG;
        float* sb = sa + 128 * GROW;
#pragma unroll
        for (int it = 0; it < 4; it++) {
            int c = it * 256 + tid, r = c >> 3, c4 = (c & 7) << 2;
            float* da = sa + r * GROW + 2 * c4;
            *(float4*)(da)     = make_float4(ha[it].x, la[it].x, ha[it].y, la[it].y);
            *(float4*)(da + 4) = make_float4(ha[it].z, la[it].z, ha[it].w, la[it].w);
            float* db = sb + r * GROW + 2 * c4;
            *(float4*)(db)     = make_float4(hb[it].x, lb[it].x, hb[it].y, lb[it].y);
            *(float4*)(db + 4) = make_float4(hb[it].z, lb[it].z, hb[it].w, lb[it].w);
        }
    };

    loadregs(0);
    storestage(0);
    __syncthreads();

    for (int k0 = 0; k0 < nk; k0++) {
        if (k0 + 1 < nk) loadregs(k0 + 1);
        const float* sa = sgm + (k0 & 1) * GSTG;
        const float* sb = sa + 128 * GROW;
#pragma unroll
        for (int kk = 0; kk < 4; kk++) {
            uint32_t ah[4][4], al[4][4], bh[4][2], bl[4][2];
#pragma unroll
            for (int mt = 0; mt < 4; mt++) {
                int ro = (wm * 64 + mt * 16 + g) * GROW + 2 * (kk * 8 + tg);
                float2 p00 = *(const float2*)(sa + ro);
                float2 p10 = *(const float2*)(sa + ro + 8 * GROW);
                float2 p01 = *(const float2*)(sa + ro + 8);
                float2 p11 = *(const float2*)(sa + ro + 8 * GROW + 8);
                ah[mt][0] = f2u(p00.x); al[mt][0] = f2u(p00.y);
                ah[mt][1] = f2u(p10.x); al[mt][1] = f2u(p10.y);
                ah[mt][2] = f2u(p01.x); al[mt][2] = f2u(p01.y);
                ah[mt][3] = f2u(p11.x); al[mt][3] = f2u(p11.y);
            }
#pragma unroll
            for (int nt = 0; nt < 4; nt++) {
                int ro = (wn * 32 + nt * 8 + g) * GROW + 2 * (kk * 8 + tg);
                float2 q0 = *(const float2*)(sb + ro);
                float2 q1 = *(const float2*)(sb + ro + 8);
                bh[nt][0] = f2u(q0.x); bl[nt][0] = f2u(q0.y);
                bh[nt][1] = f2u(q1.x); bl[nt][1] = f2u(q1.y);
            }
#pragma unroll
            for (int mt = 0; mt < 4; mt++)
#pragma unroll
                for (int nt = 0; nt < 4; nt++) {
                    mma_tf32(acc[mt][nt][0], acc[mt][nt][1], acc[mt][nt][2], acc[mt][nt][3],
                             al[mt][0], al[mt][1], al[mt][2], al[mt][3],
                             bh[nt][0], bh[nt][1]);
                    mma_tf32(acc[mt][nt][0], acc[mt][nt][1], acc[mt][nt][2], acc[mt][nt][3],
                             ah[mt][0], ah[mt][1], ah[mt][2], ah[mt][3],
                             bl[nt][0], bl[nt][1]);
                    mma_tf32(acc[mt][nt][0], acc[mt][nt][1], acc[mt][nt][2], acc[mt][nt][3],
                             ah[mt][0], ah[mt][1], ah[mt][2], ah[mt][3],
                             bh[nt][0], bh[nt][1]);
                }
        }
        if (k0 + 1 < nk) storestage((k0 + 1) & 1);
        __syncthreads();
    }

#pragma unroll
    for (int mt = 0; mt < 4; mt++) {
        int row = m0 + wm * 64 + mt * 16 + g;
#pragma unroll
        for (int nt = 0; nt < 4; nt++) {
            int col = n0 + wn * 32 + nt * 8 + tg * 2;
            *(float2*)(C + (size_t)row * N + col)       = make_float2(acc[mt][nt][0], acc[mt][nt][1]);
            *(float2*)(C + (size_t)(row + 8) * N + col) = make_float2(acc[mt][nt][2], acc[mt][nt][3]);
        }
    }
}

// ---------------------------------------------------------------------------
// Per-head RMSNorm + partial RoPE (pd=16) + optional gain. One warp per head.
// buf layout: (tok, stride) with head h at col h*HD.
// ---------------------------------------------------------------------------
__global__ void post_norm_rope(float* __restrict__ buf, const float* __restrict__ gain,
                               int nheads, int stride) {
    int head = blockIdx.x;
    int h    = head % nheads;
    int tok  = head / nheads;
    int t    = tok % TT;
    int lane = threadIdx.x;
    float* base = buf + (size_t)tok * stride + h * HD;
    float x0 = base[lane], x1 = base[lane + 32];
    float ss = x0*x0 + x1*x1;
#pragma unroll
    for (int off = 16; off; off >>= 1) ss += __shfl_xor_sync(0xffffffffu, ss, off);
    float rn = rsqrtf(ss * (1.0f/HD) + 1.1920929e-07f);
    x0 *= rn; x1 *= rn;
    float xp = __shfl_xor_sync(0xffffffffu, x0, 8);
    if (lane < 16) {
        int j = lane & 7;
        float inv = powf(10000.0f, -(float)(2*j) * (1.0f/16.0f));
        float ang = (float)t * inv;
        float s, c;
        sincosf(ang, &s, &c);
        x0 = (lane < 8) ? (x0*c + xp*s) : (xp*s - x0*c);
    }
    float gg = gain ? gain[h] : 1.0f;
    base[lane]      = x0 * gg;
    base[lane + 32] = x1 * gg;
}

// ---------------------------------------------------------------------------
// flash4: tensor-core flash attention (m16n8k8 tf32).  (proven round 14)
// Reads g_q (stride DD) and g_kv (stride KVW; v at +KD). Writes y hi/lo split.
// ---------------------------------------------------------------------------
__global__ __launch_bounds__(256, 1) void flash4() {
    extern __shared__ __align__(16) float fsm[];
    float* Khl = fsm;              // 8704 floats
    float* Vhl = fsm + 8704;       // 8704
    float* Ps  = fsm + 17408;      // 8704 (128 x 68)

    int qt = (TT/128 - 1) - blockIdx.x;      // heavy tiles first
    int h = blockIdx.y, b = blockIdx.z;
    int hkv = h / GQ;
    int tid = threadIdx.x;
    int w = tid >> 5, lane = tid & 31;
    int g = lane >> 2, tg = lane & 3;
    int q0 = qt << 7;
    int rw = q0 + w * 16;                    // warp row base

    float qh[8][4], ql[8][4];
    {
        const float* qb = g_q + ((size_t)(b*TT + rw)) * DD + h * HD;
#pragma unroll
        for (int kk = 0; kk < 8; kk++) {
            int d = kk * 8 + tg;
            float v0 = qb[(size_t)g * DD + d];
            float v1 = qb[(size_t)(g + 8) * DD + d];
            float v2 = qb[(size_t)g * DD + d + 4];
            float v3 = qb[(size_t)(g + 8) * DD + d + 4];
            qh[kk][0] = to_tf32(v0); ql[kk][0] = to_tf32(v0 - qh[kk][0]);
            qh[kk][1] = to_tf32(v1); ql[kk][1] = to_tf32(v1 - qh[kk][1]);
            qh[kk][2] = to_tf32(v2); ql[kk][2] = to_tf32(v2 - qh[kk][2]);
            qh[kk][3] = to_tf32(v3); ql[kk][3] = to_tf32(v3 - qh[kk][3]);
        }
    }

    float m0 = -1e30f, m1 = -1e30f, l0 = 0.f, l1 = 0.f;
    float o[8][4];
#pragma unroll
    for (int nt = 0; nt < 8; nt++)
#pragma unroll
        for (int r = 0; r < 4; r++) o[nt][r] = 0.f;

    int nkt = 2 * qt + 2;
    for (int kt = 0; kt < nkt; kt++) {
        __syncthreads();
        {
            int c = tid >> 2, d0 = (tid & 3) << 4;
            size_t src = (size_t)(b*TT + (kt << 6) + c) * KVW + hkv * HD + d0;
            float* kr = Khl + c * 136 + 2 * d0;
            float* vr = Vhl + c * 136 + 2 * d0;
#pragma unroll
            for (int i = 0; i < 4; i++) {
                float4 kv = *(const float4*)(g_kv + src + i * 4);
                float a0 = to_tf32(kv.x), a1 = to_tf32(kv.y), a2 = to_tf32(kv.z), a3 = to_tf32(kv.w);
                *(float4*)(kr + i*8)     = make_float4(a0, to_tf32(kv.x - a0), a1, to_tf32(kv.y - a1));
                *(float4*)(kr + i*8 + 4) = make_float4(a2, to_tf32(kv.z - a2), a3, to_tf32(kv.w - a3));
                float4 vv = *(const float4*)(g_kv + src + KD + i * 4);
                float b0 = to_tf32(vv.x), b1 = to_tf32(vv.y), b2 = to_tf32(vv.z), b3 = to_tf32(vv.w);
                *(float4*)(vr + i*8)     = make_float4(b0, to_tf32(vv.x - b0), b1, to_tf32(vv.y - b1));
                *(float4*)(vr + i*8 + 4) = make_float4(b2, to_tf32(vv.z - b2), b3, to_tf32(vv.w - b3));
            }
        }
        __syncthreads();

        // ---- S = Q K^T (tf32x3) ----
        float s[8][4];
#pragma unroll
        for (int nt = 0; nt < 8; nt++)
#pragma unroll
            for (int r = 0; r < 4; r++) s[nt][r] = 0.f;

#pragma unroll
        for (int kk = 0; kk < 8; kk++) {
#pragma unroll
            for (int nt = 0; nt < 8; nt++) {
                const float* kp = Khl + (nt * 8 + g) * 136 + 2 * (kk * 8 + tg);
                float2 p0 = *(const float2*)kp;
                float2 p1 = *(const float2*)(kp + 8);
                mma_tf32(s[nt][0], s[nt][1], s[nt][2], s[nt][3],
                         f2u(ql[kk][0]), f2u(ql[kk][1]), f2u(ql[kk][2]), f2u(ql[kk][3]),
                         f2u(p0.x), f2u(p1.x));
                mma_tf32(s[nt][0], s[nt][1], s[nt][2], s[nt][3],
                         f2u(qh[kk][0]), f2u(qh[kk][1]), f2u(qh[kk][2]), f2u(qh[kk][3]),
                         f2u(p0.y), f2u(p1.y));
                mma_tf32(s[nt][0], s[nt][1], s[nt][2], s[nt][3],
                         f2u(qh[kk][0]), f2u(qh[kk][1]), f2u(qh[kk][2]), f2u(qh[kk][3]),
                         f2u(p0.x), f2u(p1.x));
            }
        }

        // ---- scale + causal mask ----
        const float SC = 0.125f;
        if (kt >= 2 * qt) {
            int cb = kt << 6;
            int r0 = rw + g, r1 = rw + g + 8;
#pragma unroll
            for (int nt = 0; nt < 8; nt++) {
                int col = cb + nt * 8 + 2 * tg;
                s[nt][0] = (col     <= r0) ? s[nt][0] * SC : -1e30f;
                s[nt][1] = (col + 1 <= r0) ? s[nt][1] * SC : -1e30f;
                s[nt][2] = (col     <= r1) ? s[nt][2] * SC : -1e30f;
                s[nt][3] = (col + 1 <= r1) ? s[nt][3] * SC : -1e30f;
            }
        } else {
#pragma unroll
            for (int nt = 0; nt < 8; nt++)
#pragma unroll
                for (int r = 0; r < 4; r++) s[nt][r] *= SC;
        }

        // ---- online softmax ----
        float mx0 = s[0][0], mx1 = s[0][2];
#pragma unroll
        for (int nt = 0; nt < 8; nt++) {
            mx0 = fmaxf(mx0, fmaxf(s[nt][0], s[nt][1]));
            mx1 = fmaxf(mx1, fmaxf(s[nt][2], s[nt][3]));
        }
        mx0 = fmaxf(mx0, __shfl_xor_sync(0xffffffffu, mx0, 1));
        mx0 = fmaxf(mx0, __shfl_xor_sync(0xffffffffu, mx0, 2));
        mx1 = fmaxf(mx1, __shfl_xor_sync(0xffffffffu, mx1, 1));
        mx1 = fmaxf(mx1, __shfl_xor_sync(0xffffffffu, mx1, 2));
        float mn0 = fmaxf(m0, mx0), mn1 = fmaxf(m1, mx1);
        float cr0 = __expf(m0 - mn0), cr1 = __expf(m1 - mn1);
        m0 = mn0; m1 = mn1;
        float su0 = 0.f, su1 = 0.f;
#pragma unroll
        for (int nt = 0; nt < 8; nt++) {
            float p;
            p = to_tf32(__expf(s[nt][0] - mn0)); s[nt][0] = p; su0 += p;
            p = to_tf32(__expf(s[nt][1] - mn0)); s[nt][1] = p; su0 += p;
            p = to_tf32(__expf(s[nt][2] - mn1)); s[nt][2] = p; su1 += p;
            p = to_tf32(__expf(s[nt][3] - mn1)); s[nt][3] = p; su1 += p;
        }
        su0 += __shfl_xor_sync(0xffffffffu, su0, 1);
        su0 += __shfl_xor_sync(0xffffffffu, su0, 2);
        su1 += __shfl_xor_sync(0xffffffffu, su1, 1);
        su1 += __shfl_xor_sync(0xffffffffu, su1, 2);
        l0 = l0 * cr0 + su0;
        l1 = l1 * cr1 + su1;

#pragma unroll
        for (int nt = 0; nt < 8; nt++) {
            o[nt][0] *= cr0; o[nt][1] *= cr0; o[nt][2] *= cr1; o[nt][3] *= cr1;
            *(float2*)(Ps + (w*16 + g) * 68 + nt * 8 + 2 * tg)     = make_float2(s[nt][0], s[nt][1]);
            *(float2*)(Ps + (w*16 + g + 8) * 68 + nt * 8 + 2 * tg) = make_float2(s[nt][2], s[nt][3]);
        }
        __syncwarp();

        // ---- O += P V (tf32x2: V hi/lo) ----
#pragma unroll
        for (int kk = 0; kk < 8; kk++) {
            const float* pp = Ps + (w*16 + g) * 68 + kk * 8 + tg;
            uint32_t a0 = f2u(pp[0]), a1 = f2u(pp[8 * 68]), a2 = f2u(pp[4]), a3 = f2u(pp[8 * 68 + 4]);
#pragma unroll
            for (int nt = 0; nt < 8; nt++) {
                const float* vp = Vhl + (kk * 8 + tg) * 136 + 2 * (nt * 8 + g);
                float2 v0 = *(const float2*)vp;
                float2 v1 = *(const float2*)(vp + 4 * 136);
                mma_tf32(o[nt][0], o[nt][1], o[nt][2], o[nt][3],
                         a0, a1, a2, a3, f2u(v0.x), f2u(v1.x));
                mma_tf32(o[nt][0], o[nt][1], o[nt][2], o[nt][3],
                         a0, a1, a2, a3, f2u(v0.y), f2u(v1.y));
            }
        }
    }

    // ---- normalize + split-store for out-projection ----
    float i0 = 1.0f / l0, i1 = 1.0f / l1;
#pragma unroll
    for (int nt = 0; nt < 8; nt++) {
        size_t r0 = (size_t)(b*TT + rw + g) * DD + h * HD + nt * 8 + 2 * tg;
        size_t r1 = (size_t)(b*TT + rw + g + 8) * DD + h * HD + nt * 8 + 2 * tg;
        float v00 = o[nt][0] * i0, v01 = o[nt][1] * i0;
        float v10 = o[nt][2] * i1, v11 = o[nt][3] * i1;
        float h00 = to_tf32(v00), h01 = to_tf32(v01), h10 = to_tf32(v10), h11 = to_tf32(v11);
        *(float2*)(g_y_hi + r0) = make_float2(h00, h01);
        *(float2*)(g_y_lo + r0) = make_float2(to_tf32(v00 - h00), to_tf32(v01 - h01));
        *(float2*)(g_y_hi + r1) = make_float2(h10, h11);
        *(float2*)(g_y_lo + r1) = make_float2(to_tf32(v10 - h10), to_tf32(v11 - h11));
    }
}

// ---------------------------------------------------------------------------
extern "C" void kernel_launch(void* const* d_in, const int* in_sizes, int n_in,
                              void* d_out, int out_size) {
    const float* x     = (const float*)d_in[0];
    const float* Wq    = (const float*)d_in[1];
    const float* Wk    = (const float*)d_in[2];
    const float* Wv    = (const float*)d_in[3];
    const float* Wproj = (const float*)d_in[4];
    const float* qgain = (const float*)d_in[5];
    const float* Aq    = (const float*)d_in[6];
    const float* Bq    = (const float*)d_in[7];
    const float* Av    = (const float*)d_in[8];
    const float* Bv    = (const float*)d_in[9];
    float* out = (float*)d_out;

    float *pWqh, *pWql, *pWkvh, *pWkvl, *pWph, *pWpl;
    float *pxh, *pxl, *pq, *pkv, *pyh, *pyl;
    cudaGetSymbolAddress((void**)&pWqh,  g_Wq_hi);
    cudaGetSymbolAddress((void**)&pWql,  g_Wq_lo);
    cudaGetSymbolAddress((void**)&pWkvh, g_Wkv_hi);
    cudaGetSymbolAddress((void**)&pWkvl, g_Wkv_lo);
    cudaGetSymbolAddress((void**)&pWph,  g_Wp_hi);
    cudaGetSymbolAddress((void**)&pWpl,  g_Wp_lo);
    cudaGetSymbolAddress((void**)&pxh,   g_x_hi);
    cudaGetSymbolAddress((void**)&pxl,   g_x_lo);
    cudaGetSymbolAddress((void**)&pq,    g_q);
    cudaGetSymbolAddress((void**)&pkv,   g_kv);
    cudaGetSymbolAddress((void**)&pyh,   g_y_hi);
    cudaGetSymbolAddress((void**)&pyl,   g_y_lo);

    // prep: merge LoRA + split everything into tf32 hi/lo
    merge_wq_split<<<(DD*DD + 255)/256, 256>>>(Wq, Aq, Bq, pWqh, pWql);
    merge_wkv_split<<<(KVW*DD + 255)/256, 256>>>(Wk, Wv, Av, Bv, pWkvh, pWkvl);
    split_hl<<<(DD*DD + 255)/256, 256>>>(Wproj, pWph, pWpl, DD*DD);
    split_hl<<<(NTOK*DD + 255)/256, 256>>>(x, pxh, pxl, NTOK*DD);

    // projections
    int gsm = 2 * GSTG * (int)sizeof(float);   // 139264 B
    cudaFuncSetAttribute(gemm_mma4, cudaFuncAttributeMaxDynamicSharedMemorySize, gsm);
    gemm_mma4<<<dim3(DD/128, NTOK/128), 256, gsm>>>(pxh, pxl, pWqh, pWql, pq, NTOK, DD, DD);
    gemm_mma4<<<dim3(KVW/128, NTOK/128), 256, gsm>>>(pxh, pxl, pWkvh, pWkvl, pkv, NTOK, KVW, DD);

    // rmsnorm + rope (+gain for q); v untouched
    post_norm_rope<<<NTOK*NH,  32>>>(pq,  qgain,   NH,  DD);
    post_norm_rope<<<NTOK*NKV, 32>>>(pkv, nullptr, NKV, KVW);

    // tensor-core flash attention
    int fsm4 = 26112 * (int)sizeof(float);   // 104448 B
    cudaFuncSetAttribute(flash4, cudaFuncAttributeMaxDynamicSharedMemorySize, fsm4);
    flash4<<<dim3(TT/128, NH, BB), 256, fsm4>>>();

    // output projection
    gemm_mma4<<<dim3(DD/128, NTOK/128), 256, gsm>>>(pyh, pyl, pWph, pWpl, out, NTOK, DD, DD);
}

// round 16
// speedup vs baseline: 1.0420x; 1.0420x over previous
#include <cuda_runtime.h>
#include <math.h>
#include <stdint.h>

#define BB   2
#define TT   2048
#define DD   1024
#define NH   16
#define NKV  4
#define HD   64
#define KD   256
#define RANK 8
#define NTOK (BB*TT)
#define GQ   (NH/NKV)

// scratch (static device allocations — allowed)
__device__ float g_Wq[DD*DD];     // merged Wq + Bq@Aq
__device__ float g_Wv[KD*DD];     // merged Wv + Bv@Av
__device__ float g_q[NTOK*DD];
__device__ float g_k[NTOK*KD];
__device__ float g_v[NTOK*KD];
__device__ float g_y[NTOK*DD];

// ---------------- helpers ---------------------------------------------------
__device__ __forceinline__ float to_tf32(float x) {
    uint32_t u; asm("cvt.rna.tf32.f32 %0, %1;" : "=r"(u) : "f"(x));
    return __uint_as_float(u);
}
__device__ __forceinline__ uint32_t f2u(float x) { return __float_as_uint(x); }

__device__ __forceinline__ void mma_tf32(float& c0, float& c1, float& c2, float& c3,
                                         uint32_t a0, uint32_t a1, uint32_t a2, uint32_t a3,
                                         uint32_t b0, uint32_t b1) {
    asm volatile(
        "mma.sync.aligned.m16n8k8.row.col.f32.tf32.tf32.f32 "
        "{%0,%1,%2,%3}, {%4,%5,%6,%7}, {%8,%9}, {%0,%1,%2,%3};"
        : "+f"(c0), "+f"(c1), "+f"(c2), "+f"(c3)
        : "r"(a0), "r"(a1), "r"(a2), "r"(a3), "r"(b0), "r"(b1));
}

// ---------------------------------------------------------------------------
// W_eff[o,d] = W[o,d] + sum_r Bm[o,r]*Am[r,d]    (ALPHA = 1)
// ---------------------------------------------------------------------------
__global__ void merge_w(const float* __restrict__ W, const float* __restrict__ Am,
                        const float* __restrict__ Bm, float* __restrict__ out, int rows) {
    int idx = blockIdx.x * blockDim.x + threadIdx.x;
    if (idx >= rows * DD) return;
    int o = idx / DD, d = idx - o * DD;
    float acc = W[idx];
#pragma unroll
    for (int r = 0; r < RANK; r++) acc += Bm[o*RANK + r] * Am[r*DD + d];
    out[idx] = acc;
}

// ---------------------------------------------------------------------------
// gemm_mma5: tf32x3 GEMM, 512 threads / 16 warps, warp tile 32x32.
// Same smem layout + fragment mapping + math as proven gemm_mma3; only the
// work partition changed (4 warps/SMSP for LDS->HMMA latency hiding).
// ---------------------------------------------------------------------------
__global__ __launch_bounds__(512, 1)
void gemm_mma5(const float* __restrict__ A, const float* __restrict__ W,
               float* __restrict__ C, int M, int N, int K) {
    extern __shared__ __align__(16) float sgm[];
    float* sa_hi = sgm;
    float* sa_lo = sgm + 4608;
    float* sb_hi = sgm + 9216;
    float* sb_lo = sgm + 13824;

    int tid = threadIdx.x;
    int wid = tid >> 5, lane = tid & 31;
    int g = lane >> 2, tg = lane & 3;
    int wm = wid >> 2, wn = wid & 3;       // 4x4 warp grid; warp tile 32x32
    int m0 = blockIdx.y << 7, n0 = blockIdx.x << 7;

    const float* aptr = A + (size_t)m0 * K;
    const float* bptr = W + (size_t)n0 * K;

    float acc[2][4][4];
#pragma unroll
    for (int mt = 0; mt < 2; mt++)
#pragma unroll
        for (int nt = 0; nt < 4; nt++)
#pragma unroll
            for (int r = 0; r < 4; r++) acc[mt][nt][r] = 0.f;

    int nk = K >> 5;
    float4 pa[2], pb[2];
#pragma unroll
    for (int it = 0; it < 2; it++) {
        int c = it * 512 + tid, r = c >> 3, c4 = (c & 7) << 2;
        pa[it] = *(const float4*)(aptr + (size_t)r * K + c4);
        pb[it] = *(const float4*)(bptr + (size_t)r * K + c4);
    }

    for (int k0 = 0; k0 < nk; k0++) {
#pragma unroll
        for (int it = 0; it < 2; it++) {
            int c = it * 512 + tid, r = c >> 3, c4 = (c & 7) << 2;
            float av[4] = {pa[it].x, pa[it].y, pa[it].z, pa[it].w};
            float bv[4] = {pb[it].x, pb[it].y, pb[it].z, pb[it].w};
            int off = r * 36 + c4;
#pragma unroll
            for (int e = 0; e < 4; e++) {
                float ah = to_tf32(av[e]);
                sa_hi[off + e] = ah;
                sa_lo[off + e] = to_tf32(av[e] - ah);
                float bh = to_tf32(bv[e]);
                sb_hi[off + e] = bh;
                sb_lo[off + e] = to_tf32(bv[e] - bh);
            }
        }
        __syncthreads();
        if (k0 + 1 < nk) {
            int koff = (k0 + 1) * 32;
#pragma unroll
            for (int it = 0; it < 2; it++) {
                int c = it * 512 + tid, r = c >> 3, c4 = (c & 7) << 2;
                pa[it] = *(const float4*)(aptr + (size_t)r * K + koff + c4);
                pb[it] = *(const float4*)(bptr + (size_t)r * K + koff + c4);
            }
        }
#pragma unroll
        for (int kk = 0; kk < 4; kk++) {
            uint32_t ah[2][4], al[2][4], bh[4][2], bl[4][2];
#pragma unroll
            for (int mt = 0; mt < 2; mt++) {
                int off = (wm * 32 + mt * 16 + g) * 36 + kk * 8 + tg;
                ah[mt][0] = f2u(sa_hi[off]);
                ah[mt][1] = f2u(sa_hi[off + 8 * 36]);
                ah[mt][2] = f2u(sa_hi[off + 4]);
                ah[mt][3] = f2u(sa_hi[off + 8 * 36 + 4]);
                al[mt][0] = f2u(sa_lo[off]);
                al[mt][1] = f2u(sa_lo[off + 8 * 36]);
                al[mt][2] = f2u(sa_lo[off + 4]);
                al[mt][3] = f2u(sa_lo[off + 8 * 36 + 4]);
            }
#pragma unroll
            for (int nt = 0; nt < 4; nt++) {
                int off = (wn * 32 + nt * 8 + g) * 36 + kk * 8 + tg;
                bh[nt][0] = f2u(sb_hi[off]);
                bh[nt][1] = f2u(sb_hi[off + 4]);
                bl[nt][0] = f2u(sb_lo[off]);
                bl[nt][1] = f2u(sb_lo[off + 4]);
            }
#pragma unroll
            for (int mt = 0; mt < 2; mt++)
#pragma unroll
                for (int nt = 0; nt < 4; nt++) {
                    mma_tf32(acc[mt][nt][0], acc[mt][nt][1], acc[mt][nt][2], acc[mt][nt][3],
                             al[mt][0], al[mt][1], al[mt][2], al[mt][3],
                             bh[nt][0], bh[nt][1]);
                    mma_tf32(acc[mt][nt][0], acc[mt][nt][1], acc[mt][nt][2], acc[mt][nt][3],
                             ah[mt][0], ah[mt][1], ah[mt][2], ah[mt][3],
                             bl[nt][0], bl[nt][1]);
                    mma_tf32(acc[mt][nt][0], acc[mt][nt][1], acc[mt][nt][2], acc[mt][nt][3],
                             ah[mt][0], ah[mt][1], ah[mt][2], ah[mt][3],
                             bh[nt][0], bh[nt][1]);
                }
        }
        __syncthreads();
    }

#pragma unroll
    for (int mt = 0; mt < 2; mt++) {
        int row = m0 + wm * 32 + mt * 16 + g;
#pragma unroll
        for (int nt = 0; nt < 4; nt++) {
            int col = n0 + wn * 32 + nt * 8 + tg * 2;
            *(float2*)(C + (size_t)row * N + col)       = make_float2(acc[mt][nt][0], acc[mt][nt][1]);
            *(float2*)(C + (size_t)(row + 8) * N + col) = make_float2(acc[mt][nt][2], acc[mt][nt][3]);
        }
    }
}

// ---------------------------------------------------------------------------
// Per-head RMSNorm + partial RoPE (pd=16) + optional gain. One warp per head.
// ---------------------------------------------------------------------------
__global__ void post_norm_rope(float* __restrict__ buf, const float* __restrict__ gain,
                               int nheads) {
    int head = blockIdx.x;
    int h    = head % nheads;
    int tok  = head / nheads;
    int t    = tok % TT;
    int lane = threadIdx.x;
    float* base = buf + (size_t)head * HD;
    float x0 = base[lane], x1 = base[lane + 32];
    float ss = x0*x0 + x1*x1;
#pragma unroll
    for (int off = 16; off; off >>= 1) ss += __shfl_xor_sync(0xffffffffu, ss, off);
    float rn = rsqrtf(ss * (1.0f/HD) + 1.1920929e-07f);
    x0 *= rn; x1 *= rn;
    float xp = __shfl_xor_sync(0xffffffffu, x0, 8);
    if (lane < 16) {
        int j = lane & 7;
        float inv = powf(10000.0f, -(float)(2*j) * (1.0f/16.0f));
        float ang = (float)t * inv;
        float s, c;
        sincosf(ang, &s, &c);
        x0 = (lane < 8) ? (x0*c + xp*s) : (xp*s - x0*c);
    }
    float gg = gain ? gain[h] : 1.0f;
    base[lane]      = x0 * gg;
    base[lane + 32] = x1 * gg;
}

// ---------------------------------------------------------------------------
// flash4: tensor-core flash attention (m16n8k8 tf32).  (proven round 14)
// ---------------------------------------------------------------------------
__global__ __launch_bounds__(256, 1) void flash4() {
    extern __shared__ __align__(16) float fsm[];
    float* Khl = fsm;              // 8704 floats
    float* Vhl = fsm + 8704;       // 8704
    float* Ps  = fsm + 17408;      // 8704 (128 x 68)

    int qt = (TT/128 - 1) - blockIdx.x;      // heavy tiles first
    int h = blockIdx.y, b = blockIdx.z;
    int hkv = h / GQ;
    int tid = threadIdx.x;
    int w = tid >> 5, lane = tid & 31;
    int g = lane >> 2, tg = lane & 3;
    int q0 = qt << 7;
    int rw = q0 + w * 16;                    // warp row base

    float qh[8][4], ql[8][4];
    {
        const float* qb = g_q + ((size_t)(b*TT + rw) * NH + h) * HD;
#pragma unroll
        for (int kk = 0; kk < 8; kk++) {
            int d = kk * 8 + tg;
            float v0 = qb[(size_t)g * DD + d];
            float v1 = qb[(size_t)(g + 8) * DD + d];
            float v2 = qb[(size_t)g * DD + d + 4];
            float v3 = qb[(size_t)(g + 8) * DD + d + 4];
            qh[kk][0] = to_tf32(v0); ql[kk][0] = to_tf32(v0 - qh[kk][0]);
            qh[kk][1] = to_tf32(v1); ql[kk][1] = to_tf32(v1 - qh[kk][1]);
            qh[kk][2] = to_tf32(v2); ql[kk][2] = to_tf32(v2 - qh[kk][2]);
            qh[kk][3] = to_tf32(v3); ql[kk][3] = to_tf32(v3 - qh[kk][3]);
        }
    }

    float m0 = -1e30f, m1 = -1e30f, l0 = 0.f, l1 = 0.f;
    float o[8][4];
#pragma unroll
    for (int nt = 0; nt < 8; nt++)
#pragma unroll
        for (int r = 0; r < 4; r++) o[nt][r] = 0.f;

    int nkt = 2 * qt + 2;
    for (int kt = 0; kt < nkt; kt++) {
        __syncthreads();
        {
            int c = tid >> 2, d0 = (tid & 3) << 4;
            size_t src = ((size_t)((b*TT + (kt << 6) + c) * NKV + hkv)) * HD + d0;
            float* kr = Khl + c * 136 + 2 * d0;
            float* vr = Vhl + c * 136 + 2 * d0;
#pragma unroll
            for (int i = 0; i < 4; i++) {
                float4 kv = *(const float4*)(g_k + src + i * 4);
                float a0 = to_tf32(kv.x), a1 = to_tf32(kv.y), a2 = to_tf32(kv.z), a3 = to_tf32(kv.w);
                *(float4*)(kr + i*8)     = make_float4(a0, to_tf32(kv.x - a0), a1, to_tf32(kv.y - a1));
                *(float4*)(kr + i*8 + 4) = make_float4(a2, to_tf32(kv.z - a2), a3, to_tf32(kv.w - a3));
                float4 vv = *(const float4*)(g_v + src + i * 4);
                float b0 = to_tf32(vv.x), b1 = to_tf32(vv.y), b2 = to_tf32(vv.z), b3 = to_tf32(vv.w);
                *(float4*)(vr + i*8)     = make_float4(b0, to_tf32(vv.x - b0), b1, to_tf32(vv.y - b1));
                *(float4*)(vr + i*8 + 4) = make_float4(b2, to_tf32(vv.z - b2), b3, to_tf32(vv.w - b3));
            }
        }
        __syncthreads();

        // ---- S = Q K^T (tf32x3) ----
        float s[8][4];
#pragma unroll
        for (int nt = 0; nt < 8; nt++)
#pragma unroll
            for (int r = 0; r < 4; r++) s[nt][r] = 0.f;

#pragma unroll
        for (int kk = 0; kk < 8; kk++) {
#pragma unroll
            for (int nt = 0; nt < 8; nt++) {
                const float* kp = Khl + (nt * 8 + g) * 136 + 2 * (kk * 8 + tg);
                float2 p0 = *(const float2*)kp;
                float2 p1 = *(const float2*)(kp + 8);
                mma_tf32(s[nt][0], s[nt][1], s[nt][2], s[nt][3],
                         f2u(ql[kk][0]), f2u(ql[kk][1]), f2u(ql[kk][2]), f2u(ql[kk][3]),
                         f2u(p0.x), f2u(p1.x));
                mma_tf32(s[nt][0], s[nt][1], s[nt][2], s[nt][3],
                         f2u(qh[kk][0]), f2u(qh[kk][1]), f2u(qh[kk][2]), f2u(qh[kk][3]),
                         f2u(p0.y), f2u(p1.y));
                mma_tf32(s[nt][0], s[nt][1], s[nt][2], s[nt][3],
                         f2u(qh[kk][0]), f2u(qh[kk][1]), f2u(qh[kk][2]), f2u(qh[kk][3]),
                         f2u(p0.x), f2u(p1.x));
            }
        }

        // ---- scale + causal mask ----
        const float SC = 0.125f;
        if (kt >= 2 * qt) {
            int cb = kt << 6;
            int r0 = rw + g, r1 = rw + g + 8;
#pragma unroll
            for (int nt = 0; nt < 8; nt++) {
                int col = cb + nt * 8 + 2 * tg;
                s[nt][0] = (col     <= r0) ? s[nt][0] * SC : -1e30f;
                s[nt][1] = (col + 1 <= r0) ? s[nt][1] * SC : -1e30f;
                s[nt][2] = (col     <= r1) ? s[nt][2] * SC : -1e30f;
                s[nt][3] = (col + 1 <= r1) ? s[nt][3] * SC : -1e30f;
            }
        } else {
#pragma unroll
            for (int nt = 0; nt < 8; nt++)
#pragma unroll
                for (int r = 0; r < 4; r++) s[nt][r] *= SC;
        }

        // ---- online softmax ----
        float mx0 = s[0][0], mx1 = s[0][2];
#pragma unroll
        for (int nt = 0; nt < 8; nt++) {
            mx0 = fmaxf(mx0, fmaxf(s[nt][0], s[nt][1]));
            mx1 = fmaxf(mx1, fmaxf(s[nt][2], s[nt][3]));
        }
        mx0 = fmaxf(mx0, __shfl_xor_sync(0xffffffffu, mx0, 1));
        mx0 = fmaxf(mx0, __shfl_xor_sync(0xffffffffu, mx0, 2));
        mx1 = fmaxf(mx1, __shfl_xor_sync(0xffffffffu, mx1, 1));
        mx1 = fmaxf(mx1, __shfl_xor_sync(0xffffffffu, mx1, 2));
        float mn0 = fmaxf(m0, mx0), mn1 = fmaxf(m1, mx1);
        float cr0 = __expf(m0 - mn0), cr1 = __expf(m1 - mn1);
        m0 = mn0; m1 = mn1;
        float su0 = 0.f, su1 = 0.f;
#pragma unroll
        for (int nt = 0; nt < 8; nt++) {
            float p;
            p = to_tf32(__expf(s[nt][0] - mn0)); s[nt][0] = p; su0 += p;
            p = to_tf32(__expf(s[nt][1] - mn0)); s[nt][1] = p; su0 += p;
            p = to_tf32(__expf(s[nt][2] - mn1)); s[nt][2] = p; su1 += p;
            p = to_tf32(__expf(s[nt][3] - mn1)); s[nt][3] = p; su1 += p;
        }
        su0 += __shfl_xor_sync(0xffffffffu, su0, 1);
        su0 += __shfl_xor_sync(0xffffffffu, su0, 2);
        su1 += __shfl_xor_sync(0xffffffffu, su1, 1);
        su1 += __shfl_xor_sync(0xffffffffu, su1, 2);
        l0 = l0 * cr0 + su0;
        l1 = l1 * cr1 + su1;

#pragma unroll
        for (int nt = 0; nt < 8; nt++) {
            o[nt][0] *= cr0; o[nt][1] *= cr0; o[nt][2] *= cr1; o[nt][3] *= cr1;
            *(float2*)(Ps + (w*16 + g) * 68 + nt * 8 + 2 * tg)     = make_float2(s[nt][0], s[nt][1]);
            *(float2*)(Ps + (w*16 + g + 8) * 68 + nt * 8 + 2 * tg) = make_float2(s[nt][2], s[nt][3]);
        }
        __syncwarp();

        // ---- O += P V (tf32x2: V hi/lo) ----
#pragma unroll
        for (int kk = 0; kk < 8; kk++) {
            const float* pp = Ps + (w*16 + g) * 68 + kk * 8 + tg;
            uint32_t a0 = f2u(pp[0]), a1 = f2u(pp[8 * 68]), a2 = f2u(pp[4]), a3 = f2u(pp[8 * 68 + 4]);
#pragma unroll
            for (int nt = 0; nt < 8; nt++) {
                const float* vp = Vhl + (kk * 8 + tg) * 136 + 2 * (nt * 8 + g);
                float2 v0 = *(const float2*)vp;
                float2 v1 = *(const float2*)(vp + 4 * 136);
                mma_tf32(o[nt][0], o[nt][1], o[nt][2], o[nt][3],
                         a0, a1, a2, a3, f2u(v0.x), f2u(v1.x));
                mma_tf32(o[nt][0], o[nt][1], o[nt][2], o[nt][3],
                         a0, a1, a2, a3, f2u(v0.y), f2u(v1.y));
            }
        }
    }

    // ---- normalize + store ----
    float i0 = 1.0f / l0, i1 = 1.0f / l1;
#pragma unroll
    for (int nt = 0; nt < 8; nt++) {
        size_t r0 = (size_t)(b*TT + rw + g) * DD + h * HD + nt * 8 + 2 * tg;
        size_t r1 = (size_t)(b*TT + rw + g + 8) * DD + h * HD + nt * 8 + 2 * tg;
        *(float2*)(g_y + r0) = make_float2(o[nt][0] * i0, o[nt][1] * i0);
        *(float2*)(g_y + r1) = make_float2(o[nt][2] * i1, o[nt][3] * i1);
    }
}

// ---------------------------------------------------------------------------
extern "C" void kernel_launch(void* const* d_in, const int* in_sizes, int n_in,
                              void* d_out, int out_size) {
    const float* x     = (const float*)d_in[0];
    const float* Wq    = (const float*)d_in[1];
    const float* Wk    = (const float*)d_in[2];
    const float* Wv    = (const float*)d_in[3];
    const float* Wproj = (const float*)d_in[4];
    const float* qgain = (const float*)d_in[5];
    const float* Aq    = (const float*)d_in[6];
    const float* Bq    = (const float*)d_in[7];
    const float* Av    = (const float*)d_in[8];
    const float* Bv    = (const float*)d_in[9];
    float* out = (float*)d_out;

    float *pWq, *pWv, *pq, *pk, *pv, *py;
    cudaGetSymbolAddress((void**)&pWq, g_Wq);
    cudaGetSymbolAddress((void**)&pWv, g_Wv);
    cudaGetSymbolAddress((void**)&pq,  g_q);
    cudaGetSymbolAddress((void**)&pk,  g_k);
    cudaGetSymbolAddress((void**)&pv,  g_v);
    cudaGetSymbolAddress((void**)&py,  g_y);

    // fold LoRA into weights
    merge_w<<<(DD*DD + 255)/256, 256>>>(Wq, Aq, Bq, pWq, DD);
    merge_w<<<(KD*DD + 255)/256, 256>>>(Wv, Av, Bv, pWv, KD);

    // tf32x3 tensor-core projections (512-thread version)
    int gsm = 18432 * (int)sizeof(float);
    cudaFuncSetAttribute(gemm_mma5, cudaFuncAttributeMaxDynamicSharedMemorySize, gsm);
    gemm_mma5<<<dim3(DD/128, NTOK/128), 512, gsm>>>(x, pWq, pq, NTOK, DD, DD);
    gemm_mma5<<<dim3(KD/128, NTOK/128), 512, gsm>>>(x, Wk,  pk, NTOK, KD, DD);
    gemm_mma5<<<dim3(KD/128, NTOK/128), 512, gsm>>>(x, pWv, pv, NTOK, KD, DD);

    // rmsnorm + rope (+gain for q)
    post_norm_rope<<<NTOK*NH,  32>>>(pq, qgain, NH);
    post_norm_rope<<<NTOK*NKV, 32>>>(pk, nullptr, NKV);

    // tensor-core flash attention
    int fsm4 = 26112 * (int)sizeof(float);   // 104448 B
    cudaFuncSetAttribute(flash4, cudaFuncAttributeMaxDynamicSharedMemorySize, fsm4);
    flash4<<<dim3(TT/128, NH, BB), 256, fsm4>>>();

    // output projection
    gemm_mma5<<<dim3(DD/128, NTOK/128), 512, gsm>>>(py, Wproj, out, NTOK, DD, DD);
}

// round 17
// speedup vs baseline: 1.3464x; 1.2922x over previous
#include <cuda_runtime.h>
#include <cuda_bf16.h>
#include <math.h>
#include <stdint.h>

#define BB   2
#define TT   2048
#define DD   1024
#define NH   16
#define NKV  4
#define HD   64
#define KD   256
#define RANK 8
#define NTOK (BB*TT)
#define GQ   (NH/NKV)

// scratch (static device allocations — allowed)
__device__ float g_Wq[DD*DD];     // merged Wq + Bq@Aq
__device__ float g_Wv[KD*DD];     // merged Wv + Bv@Av
__device__ float g_q[NTOK*DD];
__device__ float g_k[NTOK*KD];
__device__ float g_v[NTOK*KD];
__device__ float g_y[NTOK*DD];

// ---------------- helpers ---------------------------------------------------
__device__ __forceinline__ float to_tf32(float x) {
    uint32_t u; asm("cvt.rna.tf32.f32 %0, %1;" : "=r"(u) : "f"(x));
    return __uint_as_float(u);
}
__device__ __forceinline__ uint32_t f2u(float x) { return __float_as_uint(x); }

__device__ __forceinline__ uint32_t bfpack(__nv_bfloat16 a, __nv_bfloat16 b) {
    return ((uint32_t)__bfloat16_as_ushort(b) << 16) | (uint32_t)__bfloat16_as_ushort(a);
}
// split v = hi + lo (both bf16), return packed pair builders via out params
__device__ __forceinline__ void bfsplit(float v, __nv_bfloat16& h, __nv_bfloat16& l) {
    h = __float2bfloat16_rn(v);
    l = __float2bfloat16_rn(v - __bfloat162float(h));
}

// tf32 m16n8k8 mma.sync (for flash PV path)
__device__ __forceinline__ void mma_tf32(float& c0, float& c1, float& c2, float& c3,
                                         uint32_t a0, uint32_t a1, uint32_t a2, uint32_t a3,
                                         uint32_t b0, uint32_t b1) {
    asm volatile(
        "mma.sync.aligned.m16n8k8.row.col.f32.tf32.tf32.f32 "
        "{%0,%1,%2,%3}, {%4,%5,%6,%7}, {%8,%9}, {%0,%1,%2,%3};"
        : "+f"(c0), "+f"(c1), "+f"(c2), "+f"(c3)
        : "r"(a0), "r"(a1), "r"(a2), "r"(a3), "r"(b0), "r"(b1));
}

// bf16 m16n8k16 mma.sync (2048 MACs/instr)
__device__ __forceinline__ void mma_bf16(float& c0, float& c1, float& c2, float& c3,
                                         uint32_t a0, uint32_t a1, uint32_t a2, uint32_t a3,
                                         uint32_t b0, uint32_t b1) {
    asm volatile(
        "mma.sync.aligned.m16n8k16.row.col.f32.bf16.bf16.f32 "
        "{%0,%1,%2,%3}, {%4,%5,%6,%7}, {%8,%9}, {%0,%1,%2,%3};"
        : "+f"(c0), "+f"(c1), "+f"(c2), "+f"(c3)
        : "r"(a0), "r"(a1), "r"(a2), "r"(a3), "r"(b0), "r"(b1));
}

// ---------------------------------------------------------------------------
// W_eff[o,d] = W[o,d] + sum_r Bm[o,r]*Am[r,d]    (ALPHA = 1)
// ---------------------------------------------------------------------------
__global__ void merge_w(const float* __restrict__ W, const float* __restrict__ Am,
                        const float* __restrict__ Bm, float* __restrict__ out, int rows) {
    int idx = blockIdx.x * blockDim.x + threadIdx.x;
    if (idx >= rows * DD) return;
    int o = idx / DD, d = idx - o * DD;
    float acc = W[idx];
#pragma unroll
    for (int r = 0; r < RANK; r++) acc += Bm[o*RANK + r] * Am[r*DD + d];
    out[idx] = acc;
}

// ---------------------------------------------------------------------------
// gemm_bf3: bf16x3 split-precision GEMM, C = A @ W^T (~17-bit mantissa).
// 512 threads / 16 warps, warp tile 32x32, BK=32, m16n8k16 bf16 MMA.
// smem: hi/lo bf16 tiles [128][40] (pad 40 -> conflict-free fragment loads).
// ---------------------------------------------------------------------------
__global__ __launch_bounds__(512, 1)
void gemm_bf3(const float* __restrict__ A, const float* __restrict__ W,
              float* __restrict__ C, int M, int N, int K) {
    __shared__ __align__(16) __nv_bfloat16 sa_hi[128*40];
    __shared__ __align__(16) __nv_bfloat16 sa_lo[128*40];
    __shared__ __align__(16) __nv_bfloat16 sb_hi[128*40];
    __shared__ __align__(16) __nv_bfloat16 sb_lo[128*40];

    int tid = threadIdx.x;
    int wid = tid >> 5, lane = tid & 31;
    int g = lane >> 2, tg = lane & 3;
    int wm = wid >> 2, wn = wid & 3;       // 4x4 warp grid; warp tile 32x32
    int m0 = blockIdx.y << 7, n0 = blockIdx.x << 7;

    const float* aptr = A + (size_t)m0 * K;
    const float* bptr = W + (size_t)n0 * K;

    float acc[2][4][4];
#pragma unroll
    for (int mt = 0; mt < 2; mt++)
#pragma unroll
        for (int nt = 0; nt < 4; nt++)
#pragma unroll
            for (int r = 0; r < 4; r++) acc[mt][nt][r] = 0.f;

    int nk = K >> 5;
    float4 pa[2], pb[2];
#pragma unroll
    for (int it = 0; it < 2; it++) {
        int c = it * 512 + tid, r = c >> 3, c4 = (c & 7) << 2;
        pa[it] = *(const float4*)(aptr + (size_t)r * K + c4);
        pb[it] = *(const float4*)(bptr + (size_t)r * K + c4);
    }

    for (int k0 = 0; k0 < nk; k0++) {
        // split current chunk into bf16 hi/lo and store
#pragma unroll
        for (int it = 0; it < 2; it++) {
            int c = it * 512 + tid, r = c >> 3, c4 = (c & 7) << 2;
            float av[4] = {pa[it].x, pa[it].y, pa[it].z, pa[it].w};
            float bv[4] = {pb[it].x, pb[it].y, pb[it].z, pb[it].w};
            __nv_bfloat16 h[4], l[4];
#pragma unroll
            for (int e = 0; e < 4; e++) bfsplit(av[e], h[e], l[e]);
            int off = r * 40 + c4;
            *(uint32_t*)(sa_hi + off)     = bfpack(h[0], h[1]);
            *(uint32_t*)(sa_hi + off + 2) = bfpack(h[2], h[3]);
            *(uint32_t*)(sa_lo + off)     = bfpack(l[0], l[1]);
            *(uint32_t*)(sa_lo + off + 2) = bfpack(l[2], l[3]);
#pragma unroll
            for (int e = 0; e < 4; e++) bfsplit(bv[e], h[e], l[e]);
            *(uint32_t*)(sb_hi + off)     = bfpack(h[0], h[1]);
            *(uint32_t*)(sb_hi + off + 2) = bfpack(h[2], h[3]);
            *(uint32_t*)(sb_lo + off)     = bfpack(l[0], l[1]);
            *(uint32_t*)(sb_lo + off + 2) = bfpack(l[2], l[3]);
        }
        __syncthreads();
        if (k0 + 1 < nk) {
            int koff = (k0 + 1) * 32;
#pragma unroll
            for (int it = 0; it < 2; it++) {
                int c = it * 512 + tid, r = c >> 3, c4 = (c & 7) << 2;
                pa[it] = *(const float4*)(aptr + (size_t)r * K + koff + c4);
                pb[it] = *(const float4*)(bptr + (size_t)r * K + koff + c4);
            }
        }
        // two k16 sub-chunks
#pragma unroll
        for (int kk = 0; kk < 2; kk++) {
            uint32_t ah[2][4], al[2][4], bh[4][2], bl[4][2];
#pragma unroll
            for (int mt = 0; mt < 2; mt++) {
                int off = (wm * 32 + mt * 16 + g) * 40 + kk * 16 + 2 * tg;
                ah[mt][0] = *(const uint32_t*)(sa_hi + off);
                ah[mt][1] = *(const uint32_t*)(sa_hi + off + 8 * 40);
                ah[mt][2] = *(const uint32_t*)(sa_hi + off + 8);
                ah[mt][3] = *(const uint32_t*)(sa_hi + off + 8 * 40 + 8);
                al[mt][0] = *(const uint32_t*)(sa_lo + off);
                al[mt][1] = *(const uint32_t*)(sa_lo + off + 8 * 40);
                al[mt][2] = *(const uint32_t*)(sa_lo + off + 8);
                al[mt][3] = *(const uint32_t*)(sa_lo + off + 8 * 40 + 8);
            }
#pragma unroll
            for (int nt = 0; nt < 4; nt++) {
                int off = (wn * 32 + nt * 8 + g) * 40 + kk * 16 + 2 * tg;
                bh[nt][0] = *(const uint32_t*)(sb_hi + off);
                bh[nt][1] = *(const uint32_t*)(sb_hi + off + 8);
                bl[nt][0] = *(const uint32_t*)(sb_lo + off);
                bl[nt][1] = *(const uint32_t*)(sb_lo + off + 8);
            }
#pragma unroll
            for (int mt = 0; mt < 2; mt++)
#pragma unroll
                for (int nt = 0; nt < 4; nt++) {
                    mma_bf16(acc[mt][nt][0], acc[mt][nt][1], acc[mt][nt][2], acc[mt][nt][3],
                             al[mt][0], al[mt][1], al[mt][2], al[mt][3],
                             bh[nt][0], bh[nt][1]);
                    mma_bf16(acc[mt][nt][0], acc[mt][nt][1], acc[mt][nt][2], acc[mt][nt][3],
                             ah[mt][0], ah[mt][1], ah[mt][2], ah[mt][3],
                             bl[nt][0], bl[nt][1]);
                    mma_bf16(acc[mt][nt][0], acc[mt][nt][1], acc[mt][nt][2], acc[mt][nt][3],
                             ah[mt][0], ah[mt][1], ah[mt][2], ah[mt][3],
                             bh[nt][0], bh[nt][1]);
                }
        }
        __syncthreads();
    }

#pragma unroll
    for (int mt = 0; mt < 2; mt++) {
        int row = m0 + wm * 32 + mt * 16 + g;
#pragma unroll
        for (int nt = 0; nt < 4; nt++) {
            int col = n0 + wn * 32 + nt * 8 + tg * 2;
            *(float2*)(C + (size_t)row * N + col)       = make_float2(acc[mt][nt][0], acc[mt][nt][1]);
            *(float2*)(C + (size_t)(row + 8) * N + col) = make_float2(acc[mt][nt][2], acc[mt][nt][3]);
        }
    }
}

// ---------------------------------------------------------------------------
// Per-head RMSNorm + partial RoPE (pd=16) + optional gain. One warp per head.
// ---------------------------------------------------------------------------
__global__ void post_norm_rope(float* __restrict__ buf, const float* __restrict__ gain,
                               int nheads) {
    int head = blockIdx.x;
    int h    = head % nheads;
    int tok  = head / nheads;
    int t    = tok % TT;
    int lane = threadIdx.x;
    float* base = buf + (size_t)head * HD;
    float x0 = base[lane], x1 = base[lane + 32];
    float ss = x0*x0 + x1*x1;
#pragma unroll
    for (int off = 16; off; off >>= 1) ss += __shfl_xor_sync(0xffffffffu, ss, off);
    float rn = rsqrtf(ss * (1.0f/HD) + 1.1920929e-07f);
    x0 *= rn; x1 *= rn;
    float xp = __shfl_xor_sync(0xffffffffu, x0, 8);
    if (lane < 16) {
        int j = lane & 7;
        float inv = powf(10000.0f, -(float)(2*j) * (1.0f/16.0f));
        float ang = (float)t * inv;
        float s, c;
        sincosf(ang, &s, &c);
        x0 = (lane < 8) ? (x0*c + xp*s) : (xp*s - x0*c);
    }
    float gg = gain ? gain[h] : 1.0f;
    base[lane]      = x0 * gg;
    base[lane + 32] = x1 * gg;
}

// ---------------------------------------------------------------------------
// flash5: tensor-core flash attention.
// QK = bf16x3 (m16n8k16); PV = tf32x2 (m16n8k8, proven round 14).
// smem: Khi/Klo bf16 [64][72]; Vhl float tf32 hi/lo interleaved [64][136];
//       Ps float [128][68].
// ---------------------------------------------------------------------------
__global__ __launch_bounds__(256, 1) void flash5() {
    extern __shared__ __align__(16) char fsmc[];
    __nv_bfloat16* Khi = (__nv_bfloat16*)fsmc;             //  9216 B
    __nv_bfloat16* Klo = (__nv_bfloat16*)(fsmc + 9216);    //  9216 B
    float* Vhl = (float*)(fsmc + 18432);                   // 34816 B
    float* Ps  = (float*)(fsmc + 53248);                   // 34816 B

    int qt = (TT/128 - 1) - blockIdx.x;      // heavy tiles first
    int h = blockIdx.y, b = blockIdx.z;
    int hkv = h / GQ;
    int tid = threadIdx.x;
    int w = tid >> 5, lane = tid & 31;
    int g = lane >> 2, tg = lane & 3;
    int q0 = qt << 7;
    int rw = q0 + w * 16;                    // warp row base

    // Q fragments, bf16 hi/lo pairs, rows rw+g / rw+g+8 (m16n8k16 A layout)
    uint32_t qh[4][4], ql[4][4];
    {
        const float* qb = g_q + (size_t)(b*TT + rw) * DD + h * HD;
#pragma unroll
        for (int kk = 0; kk < 4; kk++) {
            int d = kk * 16 + 2 * tg;
            __nv_bfloat16 hh[2], ll[2];
            bfsplit(qb[(size_t)g * DD + d],     hh[0], ll[0]);
            bfsplit(qb[(size_t)g * DD + d + 1], hh[1], ll[1]);
            qh[kk][0] = bfpack(hh[0], hh[1]); ql[kk][0] = bfpack(ll[0], ll[1]);
            bfsplit(qb[(size_t)(g+8) * DD + d],     hh[0], ll[0]);
            bfsplit(qb[(size_t)(g+8) * DD + d + 1], hh[1], ll[1]);
            qh[kk][1] = bfpack(hh[0], hh[1]); ql[kk][1] = bfpack(ll[0], ll[1]);
            bfsplit(qb[(size_t)g * DD + d + 8], hh[0], ll[0]);
            bfsplit(qb[(size_t)g * DD + d + 9], hh[1], ll[1]);
            qh[kk][2] = bfpack(hh[0], hh[1]); ql[kk][2] = bfpack(ll[0], ll[1]);
            bfsplit(qb[(size_t)(g+8) * DD + d + 8], hh[0], ll[0]);
            bfsplit(qb[(size_t)(g+8) * DD + d + 9], hh[1], ll[1]);
            qh[kk][3] = bfpack(hh[0], hh[1]); ql[kk][3] = bfpack(ll[0], ll[1]);
        }
    }

    float m0 = -1e30f, m1 = -1e30f, l0 = 0.f, l1 = 0.f;
    float o[8][4];
#pragma unroll
    for (int nt = 0; nt < 8; nt++)
#pragma unroll
        for (int r = 0; r < 4; r++) o[nt][r] = 0.f;

    int nkt = 2 * qt + 2;
    for (int kt = 0; kt < nkt; kt++) {
        __syncthreads();
        // cooperative K/V tile load: K -> bf16 hi/lo; V -> tf32 hi/lo interleaved
        {
            int c = tid >> 2, d0 = (tid & 3) << 4;
            size_t src = ((size_t)((b*TT + (kt << 6) + c) * NKV + hkv)) * HD + d0;
            __nv_bfloat16* krh = Khi + c * 72 + d0;
            __nv_bfloat16* krl = Klo + c * 72 + d0;
            float* vr = Vhl + c * 136 + 2 * d0;
#pragma unroll
            for (int i = 0; i < 4; i++) {
                float4 kv = *(const float4*)(g_k + src + i * 4);
                __nv_bfloat16 h0, h1, h2, h3, l0b, l1b, l2b, l3b;
                bfsplit(kv.x, h0, l0b); bfsplit(kv.y, h1, l1b);
                bfsplit(kv.z, h2, l2b); bfsplit(kv.w, h3, l3b);
                *(uint32_t*)(krh + i*4)     = bfpack(h0, h1);
                *(uint32_t*)(krh + i*4 + 2) = bfpack(h2, h3);
                *(uint32_t*)(krl + i*4)     = bfpack(l0b, l1b);
                *(uint32_t*)(krl + i*4 + 2) = bfpack(l2b, l3b);
                float4 vv = *(const float4*)(g_v + src + i * 4);
                float b0 = to_tf32(vv.x), b1 = to_tf32(vv.y), b2 = to_tf32(vv.z), b3 = to_tf32(vv.w);
                *(float4*)(vr + i*8)     = make_float4(b0, to_tf32(vv.x - b0), b1, to_tf32(vv.y - b1));
                *(float4*)(vr + i*8 + 4) = make_float4(b2, to_tf32(vv.z - b2), b3, to_tf32(vv.w - b3));
            }
        }
        __syncthreads();

        // ---- S = Q K^T (bf16x3, m16n8k16) ----
        float s[8][4];
#pragma unroll
        for (int nt = 0; nt < 8; nt++)
#pragma unroll
            for (int r = 0; r < 4; r++) s[nt][r] = 0.f;

#pragma unroll
        for (int kk = 0; kk < 4; kk++) {
#pragma unroll
            for (int nt = 0; nt < 8; nt++) {
                const __nv_bfloat16* kh = Khi + (nt * 8 + g) * 72 + kk * 16 + 2 * tg;
                const __nv_bfloat16* kl = Klo + (nt * 8 + g) * 72 + kk * 16 + 2 * tg;
                uint32_t bh0 = *(const uint32_t*)kh;
                uint32_t bh1 = *(const uint32_t*)(kh + 8);
                uint32_t bl0 = *(const uint32_t*)kl;
                uint32_t bl1 = *(const uint32_t*)(kl + 8);
                mma_bf16(s[nt][0], s[nt][1], s[nt][2], s[nt][3],
                         ql[kk][0], ql[kk][1], ql[kk][2], ql[kk][3], bh0, bh1);
                mma_bf16(s[nt][0], s[nt][1], s[nt][2], s[nt][3],
                         qh[kk][0], qh[kk][1], qh[kk][2], qh[kk][3], bl0, bl1);
                mma_bf16(s[nt][0], s[nt][1], s[nt][2], s[nt][3],
                         qh[kk][0], qh[kk][1], qh[kk][2], qh[kk][3], bh0, bh1);
            }
        }

        // ---- scale + causal mask ----
        const float SC = 0.125f;
        if (kt >= 2 * qt) {
            int cb = kt << 6;
            int r0 = rw + g, r1 = rw + g + 8;
#pragma unroll
            for (int nt = 0; nt < 8; nt++) {
                int col = cb + nt * 8 + 2 * tg;
                s[nt][0] = (col     <= r0) ? s[nt][0] * SC : -1e30f;
                s[nt][1] = (col + 1 <= r0) ? s[nt][1] * SC : -1e30f;
                s[nt][2] = (col     <= r1) ? s[nt][2] * SC : -1e30f;
                s[nt][3] = (col + 1 <= r1) ? s[nt][3] * SC : -1e30f;
            }
        } else {
#pragma unroll
            for (int nt = 0; nt < 8; nt++)
#pragma unroll
                for (int r = 0; r < 4; r++) s[nt][r] *= SC;
        }

        // ---- online softmax (rows g, g+8; 4 lanes per row) ----
        float mx0 = s[0][0], mx1 = s[0][2];
#pragma unroll
        for (int nt = 0; nt < 8; nt++) {
            mx0 = fmaxf(mx0, fmaxf(s[nt][0], s[nt][1]));
            mx1 = fmaxf(mx1, fmaxf(s[nt][2], s[nt][3]));
        }
        mx0 = fmaxf(mx0, __shfl_xor_sync(0xffffffffu, mx0, 1));
        mx0 = fmaxf(mx0, __shfl_xor_sync(0xffffffffu, mx0, 2));
        mx1 = fmaxf(mx1, __shfl_xor_sync(0xffffffffu, mx1, 1));
        mx1 = fmaxf(mx1, __shfl_xor_sync(0xffffffffu, mx1, 2));
        float mn0 = fmaxf(m0, mx0), mn1 = fmaxf(m1, mx1);
        float cr0 = __expf(m0 - mn0), cr1 = __expf(m1 - mn1);
        m0 = mn0; m1 = mn1;
        float su0 = 0.f, su1 = 0.f;
#pragma unroll
        for (int nt = 0; nt < 8; nt++) {
            float p;
            p = to_tf32(__expf(s[nt][0] - mn0)); s[nt][0] = p; su0 += p;
            p = to_tf32(__expf(s[nt][1] - mn0)); s[nt][1] = p; su0 += p;
            p = to_tf32(__expf(s[nt][2] - mn1)); s[nt][2] = p; su1 += p;
            p = to_tf32(__expf(s[nt][3] - mn1)); s[nt][3] = p; su1 += p;
        }
        su0 += __shfl_xor_sync(0xffffffffu, su0, 1);
        su0 += __shfl_xor_sync(0xffffffffu, su0, 2);
        su1 += __shfl_xor_sync(0xffffffffu, su1, 1);
        su1 += __shfl_xor_sync(0xffffffffu, su1, 2);
        l0 = l0 * cr0 + su0;
        l1 = l1 * cr1 + su1;

        // correct O, stage P (warp-private rows => __syncwarp only)
#pragma unroll
        for (int nt = 0; nt < 8; nt++) {
            o[nt][0] *= cr0; o[nt][1] *= cr0; o[nt][2] *= cr1; o[nt][3] *= cr1;
            *(float2*)(Ps + (w*16 + g) * 68 + nt * 8 + 2 * tg)     = make_float2(s[nt][0], s[nt][1]);
            *(float2*)(Ps + (w*16 + g + 8) * 68 + nt * 8 + 2 * tg) = make_float2(s[nt][2], s[nt][3]);
        }
        __syncwarp();

        // ---- O += P V (tf32x2: V hi/lo, m16n8k8) ----
#pragma unroll
        for (int kk = 0; kk < 8; kk++) {
            const float* pp = Ps + (w*16 + g) * 68 + kk * 8 + tg;
            uint32_t a0 = f2u(pp[0]), a1 = f2u(pp[8 * 68]), a2 = f2u(pp[4]), a3 = f2u(pp[8 * 68 + 4]);
#pragma unroll
            for (int nt = 0; nt < 8; nt++) {
                const float* vp = Vhl + (kk * 8 + tg) * 136 + 2 * (nt * 8 + g);
                float2 v0 = *(const float2*)vp;
                float2 v1 = *(const float2*)(vp + 4 * 136);
                mma_tf32(o[nt][0], o[nt][1], o[nt][2], o[nt][3],
                         a0, a1, a2, a3, f2u(v0.x), f2u(v1.x));
                mma_tf32(o[nt][0], o[nt][1], o[nt][2], o[nt][3],
                         a0, a1, a2, a3, f2u(v0.y), f2u(v1.y));
            }
        }
    }

    // ---- normalize + store ----
    float i0 = 1.0f / l0, i1 = 1.0f / l1;
#pragma unroll
    for (int nt = 0; nt < 8; nt++) {
        size_t r0 = (size_t)(b*TT + rw + g) * DD + h * HD + nt * 8 + 2 * tg;
        size_t r1 = (size_t)(b*TT + rw + g + 8) * DD + h * HD + nt * 8 + 2 * tg;
        *(float2*)(g_y + r0) = make_float2(o[nt][0] * i0, o[nt][1] * i0);
        *(float2*)(g_y + r1) = make_float2(o[nt][2] * i1, o[nt][3] * i1);
    }
}

// ---------------------------------------------------------------------------
extern "C" void kernel_launch(void* const* d_in, const int* in_sizes, int n_in,
                              void* d_out, int out_size) {
    const float* x     = (const float*)d_in[0];
    const float* Wq    = (const float*)d_in[1];
    const float* Wk    = (const float*)d_in[2];
    const float* Wv    = (const float*)d_in[3];
    const float* Wproj = (const float*)d_in[4];
    const float* qgain = (const float*)d_in[5];
    const float* Aq    = (const float*)d_in[6];
    const float* Bq    = (const float*)d_in[7];
    const float* Av    = (const float*)d_in[8];
    const float* Bv    = (const float*)d_in[9];
    float* out = (float*)d_out;

    float *pWq, *pWv, *pq, *pk, *pv, *py;
    cudaGetSymbolAddress((void**)&pWq, g_Wq);
    cudaGetSymbolAddress((void**)&pWv, g_Wv);
    cudaGetSymbolAddress((void**)&pq,  g_q);
    cudaGetSymbolAddress((void**)&pk,  g_k);
    cudaGetSymbolAddress((void**)&pv,  g_v);
    cudaGetSymbolAddress((void**)&py,  g_y);

    // fold LoRA into weights
    merge_w<<<(DD*DD + 255)/256, 256>>>(Wq, Aq, Bq, pWq, DD);
    merge_w<<<(KD*DD + 255)/256, 256>>>(Wv, Av, Bv, pWv, KD);

    // bf16x3 tensor-core projections
    gemm_bf3<<<dim3(DD/128, NTOK/128), 512>>>(x, pWq, pq, NTOK, DD, DD);
    gemm_bf3<<<dim3(KD/128, NTOK/128), 512>>>(x, Wk,  pk, NTOK, KD, DD);
    gemm_bf3<<<dim3(KD/128, NTOK/128), 512>>>(x, pWv, pv, NTOK, KD, DD);

    // rmsnorm + rope (+gain for q)
    post_norm_rope<<<NTOK*NH,  32>>>(pq, qgain, NH);
    post_norm_rope<<<NTOK*NKV, 32>>>(pk, nullptr, NKV);

    // tensor-core flash attention (QK bf16x3, PV tf32x2)
    int fsm5 = 88064;
    cudaFuncSetAttribute(flash5, cudaFuncAttributeMaxDynamicSharedMemorySize, fsm5);
    flash5<<<dim3(TT/128, NH, BB), 256, fsm5>>>();

    // output projection
    gemm_bf3<<<dim3(DD/128, NTOK/128), 512>>>(py, Wproj, out, NTOK, DD, DD);
}